// round 13
// baseline (speedup 1.0000x reference)
#include <cuda_runtime.h>
#include <math.h>

typedef unsigned long long ull;

#define Bq   256
#define Tq   512
#define Dq   256
#define Hq   512
#define F1q  128
#define Oq   64
#define BHq  (Bq*Hq)
#define NBLK 128
#define NT   512                // threads per block
#define RD   8                  // ring depth (slots)
#define RMASK (RD-1)
#define WST  68                 // W smem k-stride (floats)
#define AST  68                 // A chunk k-stride (floats)
#define GSTR (16*AST + 4)       // padded per-kz-group stride (1092 floats)
#define ACHUNK (8*GSTR)         // one A staging buffer (8736 floats)
#define SCH  (16*68)            // legacy chunk (head phase)
#define SMEM_ALL ((Hq*WST + 2*ACHUNK) * 4)   // 139264 + 69888 = 209,152 B

// ---------------- scratch (device globals: allocation-free rule) ----------------
__device__ float g_pre0r[RD*(size_t)BHq];   // 8-slot rings
__device__ float g_h0r [RD*(size_t)BHq];
__device__ float g_p1r [RD*(size_t)BHq];
__device__ float g_h1r [RD*(size_t)BHq];
__device__ float g_z1[Bq*F1q];
__device__ unsigned g_count;
__device__ volatile unsigned g_sense;

// per-(t,band) completion counters, each counts to 8 (one per col-tile block)
__device__ int f_pre0[Tq*4];
__device__ int f_g0 [Tq*4];
__device__ int f_g1 [Tq*4];
__device__ int f_g2 [Tq*4];
__device__ int f_fc1;

// ---------------- packed f32x2 helpers ----------------
__device__ __forceinline__ ull pack2(float lo, float hi)
{
    ull v;
    asm("mov.b64 %0, {%1, %2};" : "=l"(v) : "f"(lo), "f"(hi));
    return v;
}
__device__ __forceinline__ void unpack2(ull v, float &lo, float &hi)
{
    asm("mov.b64 {%0, %1}, %2;" : "=f"(lo), "=f"(hi) : "l"(v));
}
__device__ __forceinline__ void ffma2(ull &d, ull a, ull b)
{
    asm("fma.rn.f32x2 %0, %1, %2, %0;" : "+l"(d) : "l"(a), "l"(b));
}
__device__ __forceinline__ ull addp(ull a, ull b)
{
    ull d;
    asm("add.rn.f32x2 %0, %1, %2;" : "=l"(d) : "l"(a), "l"(b));
    return d;
}

// ---------------- sync primitives ----------------
__device__ __forceinline__ int ld_acq(const int* p)
{
    int v;
    asm volatile("ld.acquire.gpu.global.s32 %0, [%1];" : "=r"(v) : "l"(p) : "memory");
    return v;
}
__device__ __forceinline__ void wait8(const int* p)
{
    while (ld_acq(p) < 8) { }
}
__device__ __forceinline__ void pub_release(int* p)
{
    asm volatile("red.release.gpu.global.add.s32 [%0], %1;" :: "l"(p), "r"(1) : "memory");
}
#define BAR256() asm volatile("bar.sync 1, 256;" ::: "memory")

// sense-reversing grid barrier; called an even number of times per launch
__device__ __forceinline__ void grid_barrier(unsigned &sense)
{
    __syncthreads();
    if (threadIdx.x == 0) {
        unsigned ns = sense ^ 1u;
        if (atomicAdd(&g_count, 1u) == NBLK - 1u) {
            g_count = 0u;
            __threadfence();
            g_sense = ns;
        } else {
            while (g_sense != ns) { __nanosleep(32); }
        }
    }
    __syncthreads();
    sense ^= 1u;
}

// ======== K-split-8 / 8x8-per-thread GEMM:  C64x64 = A(:,K) * Wsmem^T ========
// 512 threads: kz = tid>>6 owns k-range [kz*K/8, ..); within a kz group of 64,
// thread (py,px) computes the 8x8 tile at rows py*8.., cols px*8.. (partials).
// 3 smem reduction rounds (8->4->2->1), final 64x64 staged to fb (stride 68),
// read back as (tx,ty) 2x4 tiles for the 512-thread epilogue.
// W smem layout per k row (WST floats): half-split off(n)=((n&4)?32:0)+((n>>3)<<2)+(n&3).
__device__ __forceinline__ void gemm64_kp(const float* __restrict__ A, int lda, int m0,
                                          const float* __restrict__ sW, int K,
                                          float* sA, float accf[2][4])
{
    const int tid = threadIdx.x;
    const int kz  = tid >> 6;           // 0..7
    const int pos = tid & 63;
    const int py  = pos >> 3, px = pos & 7;
    const int lrow = tid >> 3;          // 0..63 (staging row)
    const int gg   = tid & 7;           // staging kz-group
    const int K8 = K >> 3;
    const float* ap = A + (size_t)(m0 + lrow) * lda + gg*K8;

    ull acc[4][8];
    #pragma unroll
    for (int i = 0; i < 4; ++i)
        #pragma unroll
        for (int j = 0; j < 8; ++j) acc[i][j] = 0ull;

    float4 pf0 = __ldcg((const float4*)(ap + 0));
    float4 pf1 = __ldcg((const float4*)(ap + 4));
    float4 pf2 = __ldcg((const float4*)(ap + 8));
    float4 pf3 = __ldcg((const float4*)(ap + 12));

    int buf = 0;
    for (int kc = 0; kc < K8; kc += 16, buf ^= 1) {
        float* sAb = sA + buf * ACHUNK;
        {
            float* d = sAb + gg*GSTR + lrow;
            d[ 0*AST] = pf0.x; d[ 1*AST] = pf0.y; d[ 2*AST] = pf0.z; d[ 3*AST] = pf0.w;
            d[ 4*AST] = pf1.x; d[ 5*AST] = pf1.y; d[ 6*AST] = pf1.z; d[ 7*AST] = pf1.w;
            d[ 8*AST] = pf2.x; d[ 9*AST] = pf2.y; d[10*AST] = pf2.z; d[11*AST] = pf2.w;
            d[12*AST] = pf3.x; d[13*AST] = pf3.y; d[14*AST] = pf3.z; d[15*AST] = pf3.w;
        }
        __syncthreads();
        if (kc + 16 < K8) {
            pf0 = __ldcg((const float4*)(ap + kc + 16));
            pf1 = __ldcg((const float4*)(ap + kc + 20));
            pf2 = __ldcg((const float4*)(ap + kc + 24));
            pf3 = __ldcg((const float4*)(ap + kc + 28));
        }
        const float* sAk = sAb + kz*GSTR;
        const float* sWk = sW + (size_t)(kz*K8 + kc)*WST;
        #pragma unroll
        for (int kk = 0; kk < 16; ++kk) {
            const float* ar = sAk + kk*AST + (py << 3);
            ulonglong2 aLo = *(const ulonglong2*)ar;        // rows +0,+1 | +2,+3
            ulonglong2 aHi = *(const ulonglong2*)(ar + 4);  // rows +4,+5 | +6,+7
            const float* wr = sWk + kk*WST + (px << 2);
            float4 wlo = *(const float4*)wr;         // cols 8px+0..3
            float4 whi = *(const float4*)(wr + 32);  // cols 8px+4..7
            ull b0 = pack2(wlo.x, wlo.x);
            ull b1 = pack2(wlo.y, wlo.y);
            ull b2 = pack2(wlo.z, wlo.z);
            ull b3 = pack2(wlo.w, wlo.w);
            ull b4 = pack2(whi.x, whi.x);
            ull b5 = pack2(whi.y, whi.y);
            ull b6 = pack2(whi.z, whi.z);
            ull b7 = pack2(whi.w, whi.w);
            ffma2(acc[0][0], aLo.x, b0); ffma2(acc[0][1], aLo.x, b1);
            ffma2(acc[0][2], aLo.x, b2); ffma2(acc[0][3], aLo.x, b3);
            ffma2(acc[0][4], aLo.x, b4); ffma2(acc[0][5], aLo.x, b5);
            ffma2(acc[0][6], aLo.x, b6); ffma2(acc[0][7], aLo.x, b7);
            ffma2(acc[1][0], aLo.y, b0); ffma2(acc[1][1], aLo.y, b1);
            ffma2(acc[1][2], aLo.y, b2); ffma2(acc[1][3], aLo.y, b3);
            ffma2(acc[1][4], aLo.y, b4); ffma2(acc[1][5], aLo.y, b5);
            ffma2(acc[1][6], aLo.y, b6); ffma2(acc[1][7], aLo.y, b7);
            ffma2(acc[2][0], aHi.x, b0); ffma2(acc[2][1], aHi.x, b1);
            ffma2(acc[2][2], aHi.x, b2); ffma2(acc[2][3], aHi.x, b3);
            ffma2(acc[2][4], aHi.x, b4); ffma2(acc[2][5], aHi.x, b5);
            ffma2(acc[2][6], aHi.x, b6); ffma2(acc[2][7], aHi.x, b7);
            ffma2(acc[3][0], aHi.y, b0); ffma2(acc[3][1], aHi.y, b1);
            ffma2(acc[3][2], aHi.y, b2); ffma2(acc[3][3], aHi.y, b3);
            ffma2(acc[3][4], aHi.y, b4); ffma2(acc[3][5], aHi.y, b5);
            ffma2(acc[3][6], aHi.y, b6); ffma2(acc[3][7], aHi.y, b7);
        }
    }
    __syncthreads();   // mainloop reads done; sA becomes the reduction buffer

    ull* rb = (ull*)sA;
    // round 1: kz odd store (slot = (kz>>1)*64 + pos, 0..255), kz even add
    if (kz & 1) {
        const int slot = ((kz >> 1) << 6) + pos;
        #pragma unroll
        for (int i = 0; i < 4; ++i)
            #pragma unroll
            for (int j = 0; j < 8; ++j)
                rb[(i*8 + j)*256 + slot] = acc[i][j];
    }
    __syncthreads();
    if (!(kz & 1)) {
        const int slot = ((kz >> 1) << 6) + pos;
        #pragma unroll
        for (int i = 0; i < 4; ++i)
            #pragma unroll
            for (int j = 0; j < 8; ++j)
                acc[i][j] = addp(acc[i][j], rb[(i*8 + j)*256 + slot]);
    }
    __syncthreads();
    // round 2: kz 2,6 store (slot = (kz>>2)*64 + pos, 0..127), kz 0,4 add
    if (kz == 2 || kz == 6) {
        const int slot = ((kz >> 2) << 6) + pos;
        #pragma unroll
        for (int i = 0; i < 4; ++i)
            #pragma unroll
            for (int j = 0; j < 8; ++j)
                rb[(i*8 + j)*128 + slot] = acc[i][j];
    }
    __syncthreads();
    if (kz == 0 || kz == 4) {
        const int slot = ((kz >> 2) << 6) + pos;
        #pragma unroll
        for (int i = 0; i < 4; ++i)
            #pragma unroll
            for (int j = 0; j < 8; ++j)
                acc[i][j] = addp(acc[i][j], rb[(i*8 + j)*128 + slot]);
    }
    __syncthreads();
    // round 3: kz 4 stores, kz 0 adds
    if (kz == 4) {
        #pragma unroll
        for (int i = 0; i < 4; ++i)
            #pragma unroll
            for (int j = 0; j < 8; ++j)
                rb[(i*8 + j)*64 + pos] = acc[i][j];
    }
    __syncthreads();
    if (kz == 0) {
        #pragma unroll
        for (int i = 0; i < 4; ++i)
            #pragma unroll
            for (int j = 0; j < 8; ++j)
                acc[i][j] = addp(acc[i][j], rb[(i*8 + j)*64 + pos]);
    }
    __syncthreads();
    // final: kz 0 stores the 64x64 result (row stride 68, 16B-aligned rows)
    float* fb = sA;
    if (kz == 0) {
        #pragma unroll
        for (int i = 0; i < 4; ++i) {
            #pragma unroll
            for (int j = 0; j < 8; ++j) {
                float lo, hi;
                unpack2(acc[i][j], lo, hi);
                fb[((py << 3) + 2*i    )*68 + (px << 3) + j] = lo;
                fb[((py << 3) + 2*i + 1)*68 + (px << 3) + j] = hi;
            }
        }
    }
    __syncthreads();
    // readback: thread (tx,ty) owns rows 2ty..2ty+1, cols 4tx..4tx+3
    const int tx = tid & 15, ty = tid >> 4;   // ty 0..31
    #pragma unroll
    for (int i = 0; i < 2; ++i) {
        float4 v = *(const float4*)&fb[((ty << 1) + i)*68 + (tx << 2)];
        accf[i][0] = v.x; accf[i][1] = v.y; accf[i][2] = v.z; accf[i][3] = v.w;
    }
    // caller's __syncthreads() orders these reads before any sA reuse
}

// preload one 64-row W tile into half-split layout sW[k*WST + off(n)]
__device__ __forceinline__ void preload_W(const float* __restrict__ W, int ldw, int n0,
                                          int K, float* sW)
{
    const int KQ = K >> 2;
    for (int i = threadIdx.x; i < (KQ << 6); i += NT) {
        int n  = i / KQ;
        int k4 = i - n * KQ;
        int off = ((n & 4) ? 32 : 0) + ((n >> 3) << 2) + (n & 3);
        float4 v = *(const float4*)(W + (size_t)(n0 + n) * ldw + (k4 << 2));
        sW[(4*k4+0)*WST + off] = v.x;
        sW[(4*k4+1)*WST + off] = v.y;
        sW[(4*k4+2)*WST + off] = v.z;
        sW[(4*k4+3)*WST + off] = v.w;
    }
}

// ------- head-phase chunked GEMM (threads 0-255 only; named barrier 1) -------
__device__ __forceinline__ void gemm64s(const float* __restrict__ A, int lda, int m0,
                                        const float* __restrict__ W, int ldw, int n0,
                                        int K, float* sA, float* sW, float accf[4][4])
{
    const int tid  = threadIdx.x;
    const int tx   = tid & 15, ty = tid >> 4;
    const int lrow = tid >> 2;
    const int lcg  = (tid & 3) << 2;
    const float* ap = A + (size_t)(m0 + lrow) * lda + lcg;
    const float* wp = W + (size_t)(n0 + lrow) * ldw + lcg;

    ull acc[2][4];
    #pragma unroll
    for (int i = 0; i < 2; ++i)
        #pragma unroll
        for (int j = 0; j < 4; ++j) acc[i][j] = 0ull;

    float4 av = __ldcg((const float4*)ap);
    float4 wv = *(const float4*)wp;

    int buf = 0;
    for (int kc = 0; kc < K; kc += 16, buf ^= 1) {
        float* sAb = sA + buf * SCH;
        float* sWb = sW + buf * SCH;
        sAb[(lcg+0)*68 + lrow] = av.x;
        sAb[(lcg+1)*68 + lrow] = av.y;
        sAb[(lcg+2)*68 + lrow] = av.z;
        sAb[(lcg+3)*68 + lrow] = av.w;
        sWb[(lcg+0)*68 + lrow] = wv.x;
        sWb[(lcg+1)*68 + lrow] = wv.y;
        sWb[(lcg+2)*68 + lrow] = wv.z;
        sWb[(lcg+3)*68 + lrow] = wv.w;
        BAR256();
        if (kc + 16 < K) {
            av = __ldcg((const float4*)(ap + kc + 16));
            wv = *(const float4*)(wp + kc + 16);
        }
        #pragma unroll
        for (int k = 0; k < 16; ++k) {
            ulonglong2 a = *(const ulonglong2*)(sAb + k*68 + (ty << 2));
            float4 w = *(const float4*)(sWb + k*68 + (tx << 2));
            ull b0 = pack2(w.x, w.x);
            ull b1 = pack2(w.y, w.y);
            ull b2 = pack2(w.z, w.z);
            ull b3 = pack2(w.w, w.w);
            ffma2(acc[0][0], a.x, b0); ffma2(acc[0][1], a.x, b1);
            ffma2(acc[0][2], a.x, b2); ffma2(acc[0][3], a.x, b3);
            ffma2(acc[1][0], a.y, b0); ffma2(acc[1][1], a.y, b1);
            ffma2(acc[1][2], a.y, b2); ffma2(acc[1][3], a.y, b3);
        }
        BAR256();
    }

    #pragma unroll
    for (int i = 0; i < 2; ++i)
        #pragma unroll
        for (int j = 0; j < 4; ++j)
            unpack2(acc[i][j], accf[2*i][j], accf[2*i + 1][j]);
}

// ========================= single persistent kernel =========================
__global__ void __launch_bounds__(NT, 1) k_all(const float* __restrict__ x,
                                               const float* __restrict__ Wih0,
                                               const float* __restrict__ bih0,
                                               const float* __restrict__ bhh0,
                                               const float* __restrict__ Whh0,
                                               const float* __restrict__ Wih1,
                                               const float* __restrict__ bih1,
                                               const float* __restrict__ bhh1,
                                               const float* __restrict__ Whh1,
                                               const float* __restrict__ Wf1,
                                               const float* __restrict__ bf1,
                                               const float* __restrict__ Wf2,
                                               const float* __restrict__ bf2,
                                               float* __restrict__ out)
{
    extern __shared__ __align__(16) float smem[];
    float* sW = smem;               // persistent W tile (half-split layout)
    float* sA = smem + Hq*WST;      // double-buffered A staging / reduction buffer

    const int tid   = threadIdx.x;
    const int blk   = blockIdx.x;
    const int band  = blk & 3;
    const int c     = (blk >> 2) & 7;
    const int group = blk >> 5;
    const int m0    = band << 6;
    const int n0    = c << 6;
    const int tx = tid & 15, ty = tid >> 4;     // epilogue tiling (2 rows x 4 cols)
    const int col = n0 + (tx << 2);
    unsigned sense = 0u;

    // ---- phase 0: reset flags (replay), preload W, zero t=-1 ring slots ----
    {
        int i = blk*NT + tid;
        if (i < Tq*4) { f_pre0[i] = 0; f_g0[i] = 0; f_g1[i] = 0; f_g2[i] = 0; }
        if (i == Tq*4) f_fc1 = 0;
    }
    if      (group == 0) preload_W(Whh0, Hq, n0, Hq, sW);
    else if (group == 1) preload_W(Wih1, Hq, n0, Hq, sW);
    else if (group == 2) preload_W(Whh1, Hq, n0, Hq, sW);
    else                 preload_W(Wih0, Dq, n0, Dq, sW);

    for (int i = blk*NT + tid; i < BHq; i += NBLK*NT) {
        g_h0r[(size_t)(RD-1)*BHq + i] = 0.f;
        g_h1r[(size_t)(RD-1)*BHq + i] = 0.f;
    }
    __threadfence();
    grid_barrier(sense);    // barrier #1

    float acc[2][4];

    // ---- phase 1: self-timed scan ----
    if (group == 3) {
        float4 b1 = *(const float4*)(bih0 + col);
        float4 b2 = *(const float4*)(bhh0 + col);
        for (int t = 0; t < Tq; ++t) {
            gemm64_kp(x + (size_t)t*Dq, Tq*Dq, m0, sW, Dq, sA, acc);
            __syncthreads();
            if (tid == 0 && t >= RD) wait8(&f_g0[(t-RD)*4 + band]);  // slot reusable
            __syncthreads();
            float* dst = g_pre0r + (size_t)(t & RMASK)*BHq;
            #pragma unroll
            for (int i = 0; i < 2; ++i) {
                int row = m0 + (ty << 1) + i;
                float4 o;
                o.x = acc[i][0] + b1.x + b2.x;
                o.y = acc[i][1] + b1.y + b2.y;
                o.z = acc[i][2] + b1.z + b2.z;
                o.w = acc[i][3] + b1.w + b2.w;
                *(float4*)(dst + (size_t)row*Hq + col) = o;
            }
            __syncthreads();
            if (tid == 0) pub_release(&f_pre0[t*4 + band]);
        }
    } else if (group == 0) {
        for (int t = 0; t < Tq; ++t) {
            if (tid == 0 && t >= 1) wait8(&f_g0[(t-1)*4 + band]);    // critical wait
            __syncthreads();
            const float* A = g_h0r + (size_t)((t-1) & RMASK)*BHq;
            gemm64_kp(A, Hq, m0, sW, Hq, sA, acc);
            __syncthreads();
            if (tid == 0) {
                wait8(&f_pre0[t*4 + band]);
                if (t >= RD) wait8(&f_g1[(t-RD)*4 + band]);
            }
            __syncthreads();
            const float* pin = g_pre0r + (size_t)(t & RMASK)*BHq;
            float* dst = g_h0r + (size_t)(t & RMASK)*BHq;
            #pragma unroll
            for (int i = 0; i < 2; ++i) {
                int row = m0 + (ty << 1) + i;
                float4 p = __ldcg((const float4*)(pin + (size_t)row*Hq + col));
                float4 o;
                o.x = tanhf(acc[i][0] + p.x);
                o.y = tanhf(acc[i][1] + p.y);
                o.z = tanhf(acc[i][2] + p.z);
                o.w = tanhf(acc[i][3] + p.w);
                *(float4*)(dst + (size_t)row*Hq + col) = o;
            }
            __syncthreads();
            if (tid == 0) pub_release(&f_g0[t*4 + band]);
        }
    } else if (group == 1) {
        float4 b1 = *(const float4*)(bih1 + col);
        float4 b2 = *(const float4*)(bhh1 + col);
        for (int t = 0; t < Tq; ++t) {
            if (tid == 0) wait8(&f_g0[t*4 + band]);
            __syncthreads();
            const float* A = g_h0r + (size_t)(t & RMASK)*BHq;
            gemm64_kp(A, Hq, m0, sW, Hq, sA, acc);
            __syncthreads();
            if (tid == 0 && t >= RD) wait8(&f_g2[(t-RD)*4 + band]);
            __syncthreads();
            float* dst = g_p1r + (size_t)(t & RMASK)*BHq;
            #pragma unroll
            for (int i = 0; i < 2; ++i) {
                int row = m0 + (ty << 1) + i;
                float4 o;
                o.x = acc[i][0] + b1.x + b2.x;
                o.y = acc[i][1] + b1.y + b2.y;
                o.z = acc[i][2] + b1.z + b2.z;
                o.w = acc[i][3] + b1.w + b2.w;
                *(float4*)(dst + (size_t)row*Hq + col) = o;
            }
            __syncthreads();
            if (tid == 0) pub_release(&f_g1[t*4 + band]);
        }
    } else {
        for (int t = 0; t < Tq; ++t) {
            if (tid == 0 && t >= 1) wait8(&f_g2[(t-1)*4 + band]);    // critical wait
            __syncthreads();
            const float* A = g_h1r + (size_t)((t-1) & RMASK)*BHq;
            gemm64_kp(A, Hq, m0, sW, Hq, sA, acc);
            __syncthreads();
            if (tid == 0) wait8(&f_g1[t*4 + band]);
            __syncthreads();
            const float* pin = g_p1r + (size_t)(t & RMASK)*BHq;
            float* dst = g_h1r + (size_t)(t & RMASK)*BHq;
            #pragma unroll
            for (int i = 0; i < 2; ++i) {
                int row = m0 + (ty << 1) + i;
                float4 p = __ldcg((const float4*)(pin + (size_t)row*Hq + col));
                float4 o;
                o.x = tanhf(acc[i][0] + p.x);
                o.y = tanhf(acc[i][1] + p.y);
                o.z = tanhf(acc[i][2] + p.z);
                o.w = tanhf(acc[i][3] + p.w);
                *(float4*)(dst + (size_t)row*Hq + col) = o;
            }
            __syncthreads();
            if (tid == 0) pub_release(&f_g2[t*4 + band]);
        }
    }

    __threadfence();        // final ring stores visible to head readers
    grid_barrier(sense);    // barrier #2 (sense back to 0)

    // ---- phase 2: head on threads 0-255 (named barrier); others exit ----
    if (tid < 256) {
        float* hA = smem;
        float* hW = smem + 2*SCH;
        float hacc[4][4];
        const int htx = tid & 15, hty = tid >> 4;

        if (blk < 8) {
            const int hm0 = (blk & 3) << 6;
            const int hn0 = (blk >> 2) << 6;
            const float* A = g_h1r + (size_t)((Tq-1) & RMASK)*BHq;
            gemm64s(A, Hq, hm0, Wf1, Hq, hn0, Hq, hA, hW, hacc);
            const int hcol = hn0 + (htx << 2);
            float4 b = *(const float4*)(bf1 + hcol);
            #pragma unroll
            for (int i = 0; i < 4; ++i) {
                int row = hm0 + (hty << 2) + i;
                float4 o;
                o.x = fmaxf(hacc[i][0] + b.x, 0.f);
                o.y = fmaxf(hacc[i][1] + b.y, 0.f);
                o.z = fmaxf(hacc[i][2] + b.z, 0.f);
                o.w = fmaxf(hacc[i][3] + b.w, 0.f);
                *(float4*)(g_z1 + (size_t)row*F1q + hcol) = o;
            }
            BAR256();
            if (tid == 0) pub_release(&f_fc1);
        } else if (blk < 12) {
            if (tid == 0) wait8(&f_fc1);
            BAR256();
            const int hm0 = (blk - 8) << 6;
            gemm64s(g_z1, F1q, hm0, Wf2, F1q, 0, F1q, hA, hW, hacc);
            const int hcol = htx << 2;
            float4 b = *(const float4*)(bf2 + hcol);
            #pragma unroll
            for (int i = 0; i < 4; ++i) {
                int row = hm0 + (hty << 2) + i;
                float4 o;
                o.x = hacc[i][0] + b.x;
                o.y = hacc[i][1] + b.y;
                o.z = hacc[i][2] + b.z;
                o.w = hacc[i][3] + b.w;
                *(float4*)(out + (size_t)row*Oq + hcol) = o;
            }
        }
    }
}

// ---------------- launch ----------------
extern "C" void kernel_launch(void* const* d_in, const int* in_sizes, int n_in,
                              void* d_out, int out_size)
{
    (void)in_sizes; (void)n_in; (void)out_size;
    const float* x    = (const float*)d_in[0];
    const float* Wih0 = (const float*)d_in[1];
    const float* Whh0 = (const float*)d_in[2];
    const float* bih0 = (const float*)d_in[3];
    const float* bhh0 = (const float*)d_in[4];
    const float* Wih1 = (const float*)d_in[5];
    const float* Whh1 = (const float*)d_in[6];
    const float* bih1 = (const float*)d_in[7];
    const float* bhh1 = (const float*)d_in[8];
    const float* Wf1  = (const float*)d_in[9];
    const float* bf1  = (const float*)d_in[10];
    const float* Wf2  = (const float*)d_in[11];
    const float* bf2  = (const float*)d_in[12];
    float* out = (float*)d_out;

    cudaFuncSetAttribute(k_all, cudaFuncAttributeMaxDynamicSharedMemorySize, SMEM_ALL);

    k_all<<<NBLK, NT, SMEM_ALL>>>(x, Wih0, bih0, bhh0, Whh0,
                                  Wih1, bih1, bhh1, Whh1,
                                  Wf1, bf1, Wf2, bf2, out);
}

// round 14
// speedup vs baseline: 1.1677x; 1.1677x over previous
#include <cuda_runtime.h>
#include <math.h>

typedef unsigned long long ull;

#define Bq   256
#define Tq   512
#define Dq   256
#define Hq   512
#define F1q  128
#define Oq   64
#define BHq  (Bq*Hq)
#define NBLK 128
#define NT   256                // threads per block (256-reg budget, no spill)
#define RD   8                  // ring depth (slots)
#define RMASK (RD-1)
#define WST  68                 // W smem k-stride (floats)
#define AST  68                 // A chunk k-stride (floats)
#define ACHUNK (4*16*AST)       // one A staging buffer: 4 kz-groups x 16 k
#define SCH  (16*68)            // legacy chunk (head phase)
#define SMEM_ALL ((Hq*WST + 2*ACHUNK) * 4)   // 139264 + 34816 = 174,080 B

// ---------------- scratch (device globals: allocation-free rule) ----------------
__device__ float g_pre0r[RD*(size_t)BHq];   // 8-slot rings
__device__ float g_h0r [RD*(size_t)BHq];
__device__ float g_p1r [RD*(size_t)BHq];
__device__ float g_h1r [RD*(size_t)BHq];
__device__ float g_z1[Bq*F1q];
__device__ unsigned g_count;
__device__ volatile unsigned g_sense;

// per-(t,band) completion counters, each counts to 8 (one per col-tile block)
__device__ int f_pre0[Tq*4];
__device__ int f_g0 [Tq*4];
__device__ int f_g1 [Tq*4];
__device__ int f_g2 [Tq*4];
__device__ int f_fc1;

// ---------------- packed f32x2 helpers ----------------
__device__ __forceinline__ ull pack2(float lo, float hi)
{
    ull v;
    asm("mov.b64 %0, {%1, %2};" : "=l"(v) : "f"(lo), "f"(hi));
    return v;
}
__device__ __forceinline__ void unpack2(ull v, float &lo, float &hi)
{
    asm("mov.b64 {%0, %1}, %2;" : "=f"(lo), "=f"(hi) : "l"(v));
}
__device__ __forceinline__ void ffma2(ull &d, ull a, ull b)
{
    asm("fma.rn.f32x2 %0, %1, %2, %0;" : "+l"(d) : "l"(a), "l"(b));
}
__device__ __forceinline__ ull addp(ull a, ull b)
{
    ull d;
    asm("add.rn.f32x2 %0, %1, %2;" : "=l"(d) : "l"(a), "l"(b));
    return d;
}

// ---------------- sync primitives ----------------
__device__ __forceinline__ int ld_acq(const int* p)
{
    int v;
    asm volatile("ld.acquire.gpu.global.s32 %0, [%1];" : "=r"(v) : "l"(p) : "memory");
    return v;
}
__device__ __forceinline__ void wait8(const int* p)
{
    while (ld_acq(p) < 8) { }
}
__device__ __forceinline__ void pub_release(int* p)
{
    asm volatile("red.release.gpu.global.add.s32 [%0], %1;" :: "l"(p), "r"(1) : "memory");
}

// sense-reversing grid barrier; called an even number of times per launch
__device__ __forceinline__ void grid_barrier(unsigned &sense)
{
    __syncthreads();
    if (threadIdx.x == 0) {
        unsigned ns = sense ^ 1u;
        if (atomicAdd(&g_count, 1u) == NBLK - 1u) {
            g_count = 0u;
            __threadfence();
            g_sense = ns;
        } else {
            while (g_sense != ns) { __nanosleep(32); }
        }
    }
    __syncthreads();
    sense ^= 1u;
}

// ======== K-split-4 / 8x8-per-thread GEMM, software-pipelined operands ========
// 256 threads: kz = tid>>6 owns k-range [kz*K/4, ..); within a kz group of 64,
// thread (py,px) computes the 8x8 tile at rows py*8.., cols px*8.. (partials).
// Inner loop: operands for k+1 are loaded (LDS) BEFORE k's 32 FFMA2, giving each
// LDS a ~64-cycle independent-FFMA shadow (hides the 29-cyc LDS latency with
// only 2 warps/SMSP). Cross-kz reduction in smem, final 64x64 staged + readback.
// W smem layout per k row (WST floats): half-split off(n)=((n&4)?32:0)+((n>>3)<<2)+(n&3).
__device__ __forceinline__ void gemm64_kp(const float* __restrict__ A, int lda, int m0,
                                          const float* __restrict__ sW, int K,
                                          float* sA, float accf[4][4])
{
    const int tid = threadIdx.x;
    const int kz  = tid >> 6;
    const int pos = tid & 63;
    const int py  = pos >> 3, px = pos & 7;
    const int lrow = tid >> 2;          // 0..63 (staging row)
    const int kr   = (tid & 3) << 2;    // 0,4,8,12 (staging k offset)
    const int K4 = K >> 2;
    const float* ap = A + (size_t)(m0 + lrow) * lda + kr;

    ull acc[4][8];
    #pragma unroll
    for (int i = 0; i < 4; ++i)
        #pragma unroll
        for (int j = 0; j < 8; ++j) acc[i][j] = 0ull;

    float4 pf0 = __ldcg((const float4*)(ap + 0*K4));
    float4 pf1 = __ldcg((const float4*)(ap + 1*K4));
    float4 pf2 = __ldcg((const float4*)(ap + 2*K4));
    float4 pf3 = __ldcg((const float4*)(ap + 3*K4));

    int buf = 0;
    for (int kc = 0; kc < K4; kc += 16, buf ^= 1) {
        float* sAb = sA + buf * ACHUNK;
        {
            float* d0 = sAb + (0*16 + kr)*AST + lrow;
            d0[0*AST] = pf0.x; d0[1*AST] = pf0.y; d0[2*AST] = pf0.z; d0[3*AST] = pf0.w;
            float* d1 = sAb + (1*16 + kr)*AST + lrow;
            d1[0*AST] = pf1.x; d1[1*AST] = pf1.y; d1[2*AST] = pf1.z; d1[3*AST] = pf1.w;
            float* d2 = sAb + (2*16 + kr)*AST + lrow;
            d2[0*AST] = pf2.x; d2[1*AST] = pf2.y; d2[2*AST] = pf2.z; d2[3*AST] = pf2.w;
            float* d3 = sAb + (3*16 + kr)*AST + lrow;
            d3[0*AST] = pf3.x; d3[1*AST] = pf3.y; d3[2*AST] = pf3.z; d3[3*AST] = pf3.w;
        }
        __syncthreads();
        if (kc + 16 < K4) {
            pf0 = __ldcg((const float4*)(ap + 0*K4 + kc + 16));
            pf1 = __ldcg((const float4*)(ap + 1*K4 + kc + 16));
            pf2 = __ldcg((const float4*)(ap + 2*K4 + kc + 16));
            pf3 = __ldcg((const float4*)(ap + 3*K4 + kc + 16));
        }
        const float* sAk = sAb + kz*(16*AST) + (py << 3);
        const float* sWk = sW + (size_t)(kz*K4 + kc)*WST + (px << 2);

        // software pipeline: preload k=0 operands
        ulonglong2 aLo = *(const ulonglong2*)sAk;
        ulonglong2 aHi = *(const ulonglong2*)(sAk + 4);
        float4 wlo = *(const float4*)sWk;
        float4 whi = *(const float4*)(sWk + 32);

        #pragma unroll
        for (int kk = 0; kk < 16; ++kk) {
            // load k+1 operands first (independent of this k's FFMA block)
            const int kn = (kk + 1) & 15;   // wrap at 15: harmless re-read of k=0
            const float* arn = sAk + kn*AST;
            const float* wrn = sWk + kn*WST;
            ulonglong2 naLo = *(const ulonglong2*)arn;
            ulonglong2 naHi = *(const ulonglong2*)(arn + 4);
            float4 nwlo = *(const float4*)wrn;
            float4 nwhi = *(const float4*)(wrn + 32);

            ull b0 = pack2(wlo.x, wlo.x);
            ull b1 = pack2(wlo.y, wlo.y);
            ull b2 = pack2(wlo.z, wlo.z);
            ull b3 = pack2(wlo.w, wlo.w);
            ull b4 = pack2(whi.x, whi.x);
            ull b5 = pack2(whi.y, whi.y);
            ull b6 = pack2(whi.z, whi.z);
            ull b7 = pack2(whi.w, whi.w);
            ffma2(acc[0][0], aLo.x, b0); ffma2(acc[0][1], aLo.x, b1);
            ffma2(acc[0][2], aLo.x, b2); ffma2(acc[0][3], aLo.x, b3);
            ffma2(acc[0][4], aLo.x, b4); ffma2(acc[0][5], aLo.x, b5);
            ffma2(acc[0][6], aLo.x, b6); ffma2(acc[0][7], aLo.x, b7);
            ffma2(acc[1][0], aLo.y, b0); ffma2(acc[1][1], aLo.y, b1);
            ffma2(acc[1][2], aLo.y, b2); ffma2(acc[1][3], aLo.y, b3);
            ffma2(acc[1][4], aLo.y, b4); ffma2(acc[1][5], aLo.y, b5);
            ffma2(acc[1][6], aLo.y, b6); ffma2(acc[1][7], aLo.y, b7);
            ffma2(acc[2][0], aHi.x, b0); ffma2(acc[2][1], aHi.x, b1);
            ffma2(acc[2][2], aHi.x, b2); ffma2(acc[2][3], aHi.x, b3);
            ffma2(acc[2][4], aHi.x, b4); ffma2(acc[2][5], aHi.x, b5);
            ffma2(acc[2][6], aHi.x, b6); ffma2(acc[2][7], aHi.x, b7);
            ffma2(acc[3][0], aHi.y, b0); ffma2(acc[3][1], aHi.y, b1);
            ffma2(acc[3][2], aHi.y, b2); ffma2(acc[3][3], aHi.y, b3);
            ffma2(acc[3][4], aHi.y, b4); ffma2(acc[3][5], aHi.y, b5);
            ffma2(acc[3][6], aHi.y, b6); ffma2(acc[3][7], aHi.y, b7);

            aLo = naLo; aHi = naHi; wlo = nwlo; whi = nwhi;
        }
    }
    __syncthreads();   // mainloop reads done; sA becomes the reduction buffer

    ull* rb = (ull*)sA;
    // round 1: kz 1,3 store (slot = (kz>>1)*64 + pos), kz 0,2 add
    if (kz & 1) {
        const int slot = ((kz >> 1) << 6) + pos;
        #pragma unroll
        for (int i = 0; i < 4; ++i)
            #pragma unroll
            for (int j = 0; j < 8; ++j)
                rb[(i*8 + j)*128 + slot] = acc[i][j];
    }
    __syncthreads();
    if (!(kz & 1)) {
        const int slot = ((kz >> 1) << 6) + pos;
        #pragma unroll
        for (int i = 0; i < 4; ++i)
            #pragma unroll
            for (int j = 0; j < 8; ++j)
                acc[i][j] = addp(acc[i][j], rb[(i*8 + j)*128 + slot]);
    }
    __syncthreads();
    // round 2: kz 2 stores, kz 0 adds
    if (kz == 2) {
        #pragma unroll
        for (int i = 0; i < 4; ++i)
            #pragma unroll
            for (int j = 0; j < 8; ++j)
                rb[(i*8 + j)*64 + pos] = acc[i][j];
    }
    __syncthreads();
    if (kz == 0) {
        #pragma unroll
        for (int i = 0; i < 4; ++i)
            #pragma unroll
            for (int j = 0; j < 8; ++j)
                acc[i][j] = addp(acc[i][j], rb[(i*8 + j)*64 + pos]);
    }
    __syncthreads();
    // round 3: kz 0 stores the final 64x64 (row-major, stride 64)
    float* fb = sA;
    if (kz == 0) {
        #pragma unroll
        for (int i = 0; i < 4; ++i) {
            #pragma unroll
            for (int j = 0; j < 8; ++j) {
                float lo, hi;
                unpack2(acc[i][j], lo, hi);
                fb[((py << 3) + 2*i    )*64 + (px << 3) + j] = lo;
                fb[((py << 3) + 2*i + 1)*64 + (px << 3) + j] = hi;
            }
        }
    }
    __syncthreads();
    // read back in the standard epilogue layout: thread (tx,ty) owns 4x4
    const int tx = tid & 15, ty = tid >> 4;
    #pragma unroll
    for (int i = 0; i < 4; ++i) {
        float4 v = *(const float4*)&fb[((ty << 2) + i)*64 + (tx << 2)];
        accf[i][0] = v.x; accf[i][1] = v.y; accf[i][2] = v.z; accf[i][3] = v.w;
    }
    // caller's __syncthreads() orders these reads before any sA reuse
}

// preload one 64-row W tile into half-split layout sW[k*WST + off(n)]
__device__ __forceinline__ void preload_W(const float* __restrict__ W, int ldw, int n0,
                                          int K, float* sW)
{
    const int KQ = K >> 2;
    for (int i = threadIdx.x; i < (KQ << 6); i += NT) {
        int n  = i / KQ;
        int k4 = i - n * KQ;
        int off = ((n & 4) ? 32 : 0) + ((n >> 3) << 2) + (n & 3);
        float4 v = *(const float4*)(W + (size_t)(n0 + n) * ldw + (k4 << 2));
        sW[(4*k4+0)*WST + off] = v.x;
        sW[(4*k4+1)*WST + off] = v.y;
        sW[(4*k4+2)*WST + off] = v.z;
        sW[(4*k4+3)*WST + off] = v.w;
    }
}

// ---------------- chunked GEMM core (head phase; A via __ldcg) ----------------
__device__ __forceinline__ void gemm64s(const float* __restrict__ A, int lda, int m0,
                                        const float* __restrict__ W, int ldw, int n0,
                                        int K, float* sA, float* sW, float accf[4][4])
{
    const int tid  = threadIdx.x;
    const int tx   = tid & 15, ty = tid >> 4;
    const int lrow = tid >> 2;
    const int lcg  = (tid & 3) << 2;
    const float* ap = A + (size_t)(m0 + lrow) * lda + lcg;
    const float* wp = W + (size_t)(n0 + lrow) * ldw + lcg;

    ull acc[2][4];
    #pragma unroll
    for (int i = 0; i < 2; ++i)
        #pragma unroll
        for (int j = 0; j < 4; ++j) acc[i][j] = 0ull;

    float4 av = __ldcg((const float4*)ap);
    float4 wv = *(const float4*)wp;

    int buf = 0;
    for (int kc = 0; kc < K; kc += 16, buf ^= 1) {
        float* sAb = sA + buf * SCH;
        float* sWb = sW + buf * SCH;
        sAb[(lcg+0)*68 + lrow] = av.x;
        sAb[(lcg+1)*68 + lrow] = av.y;
        sAb[(lcg+2)*68 + lrow] = av.z;
        sAb[(lcg+3)*68 + lrow] = av.w;
        sWb[(lcg+0)*68 + lrow] = wv.x;
        sWb[(lcg+1)*68 + lrow] = wv.y;
        sWb[(lcg+2)*68 + lrow] = wv.z;
        sWb[(lcg+3)*68 + lrow] = wv.w;
        __syncthreads();
        if (kc + 16 < K) {
            av = __ldcg((const float4*)(ap + kc + 16));
            wv = *(const float4*)(wp + kc + 16);
        }
        #pragma unroll
        for (int k = 0; k < 16; ++k) {
            ulonglong2 a = *(const ulonglong2*)(sAb + k*68 + (ty << 2));
            float4 w = *(const float4*)(sWb + k*68 + (tx << 2));
            ull b0 = pack2(w.x, w.x);
            ull b1 = pack2(w.y, w.y);
            ull b2 = pack2(w.z, w.z);
            ull b3 = pack2(w.w, w.w);
            ffma2(acc[0][0], a.x, b0); ffma2(acc[0][1], a.x, b1);
            ffma2(acc[0][2], a.x, b2); ffma2(acc[0][3], a.x, b3);
            ffma2(acc[1][0], a.y, b0); ffma2(acc[1][1], a.y, b1);
            ffma2(acc[1][2], a.y, b2); ffma2(acc[1][3], a.y, b3);
        }
        __syncthreads();
    }

    #pragma unroll
    for (int i = 0; i < 2; ++i)
        #pragma unroll
        for (int j = 0; j < 4; ++j)
            unpack2(acc[i][j], accf[2*i][j], accf[2*i + 1][j]);
}

// ========================= single persistent kernel =========================
// Phase 0 (init): reset flags (replay), preload W, zero t=-1 ring slots.
// Phase 1 (scan): 4 groups x 4 bands x 8 col-tiles, self-timed via counters.
// Phase 2 (head): blocks 0-7 fc1, blocks 8-11 fc2 (smem reused, low region).
// grid_barrier called exactly TWICE -> g_sense parity returns to 0 (replay-safe).
__global__ void __launch_bounds__(NT) k_all(const float* __restrict__ x,
                                            const float* __restrict__ Wih0,
                                            const float* __restrict__ bih0,
                                            const float* __restrict__ bhh0,
                                            const float* __restrict__ Whh0,
                                            const float* __restrict__ Wih1,
                                            const float* __restrict__ bih1,
                                            const float* __restrict__ bhh1,
                                            const float* __restrict__ Whh1,
                                            const float* __restrict__ Wf1,
                                            const float* __restrict__ bf1,
                                            const float* __restrict__ Wf2,
                                            const float* __restrict__ bf2,
                                            float* __restrict__ out)
{
    extern __shared__ __align__(16) float smem[];
    float* sW = smem;               // persistent W tile (half-split layout)
    float* sA = smem + Hq*WST;      // double-buffered A staging / reduction buffer

    const int tid   = threadIdx.x;
    const int blk   = blockIdx.x;
    const int band  = blk & 3;
    const int c     = (blk >> 2) & 7;
    const int group = blk >> 5;
    const int m0    = band << 6;
    const int n0    = c << 6;
    const int tx = tid & 15, ty = tid >> 4;
    const int col = n0 + (tx << 2);
    unsigned sense = 0u;

    // ---- phase 0: reset flags from previous replay ----
    {
        int i = blk*NT + tid;
        if (i < Tq*4) { f_pre0[i] = 0; f_g0[i] = 0; f_g1[i] = 0; f_g2[i] = 0; }
        if (i == Tq*4) f_fc1 = 0;
    }
    if      (group == 0) preload_W(Whh0, Hq, n0, Hq, sW);
    else if (group == 1) preload_W(Wih1, Hq, n0, Hq, sW);
    else if (group == 2) preload_W(Whh1, Hq, n0, Hq, sW);
    else                 preload_W(Wih0, Dq, n0, Dq, sW);

    for (int i = blk*NT + tid; i < BHq; i += NBLK*NT) {
        g_h0r[(size_t)(RD-1)*BHq + i] = 0.f;
        g_h1r[(size_t)(RD-1)*BHq + i] = 0.f;
    }
    __threadfence();
    grid_barrier(sense);    // barrier #1

    float acc[4][4];

    // ---- phase 1: self-timed scan ----
    if (group == 3) {
        float4 b1 = *(const float4*)(bih0 + col);
        float4 b2 = *(const float4*)(bhh0 + col);
        for (int t = 0; t < Tq; ++t) {
            gemm64_kp(x + (size_t)t*Dq, Tq*Dq, m0, sW, Dq, sA, acc);
            __syncthreads();
            if (tid == 0 && t >= RD) wait8(&f_g0[(t-RD)*4 + band]);  // slot reusable
            __syncthreads();
            float* dst = g_pre0r + (size_t)(t & RMASK)*BHq;
            #pragma unroll
            for (int i = 0; i < 4; ++i) {
                int row = m0 + (ty << 2) + i;
                float4 o;
                o.x = acc[i][0] + b1.x + b2.x;
                o.y = acc[i][1] + b1.y + b2.y;
                o.z = acc[i][2] + b1.z + b2.z;
                o.w = acc[i][3] + b1.w + b2.w;
                *(float4*)(dst + (size_t)row*Hq + col) = o;
            }
            __syncthreads();
            if (tid == 0) pub_release(&f_pre0[t*4 + band]);
        }
    } else if (group == 0) {
        for (int t = 0; t < Tq; ++t) {
            if (tid == 0 && t >= 1) wait8(&f_g0[(t-1)*4 + band]);    // critical wait
            __syncthreads();
            const float* A = g_h0r + (size_t)((t-1) & RMASK)*BHq;
            gemm64_kp(A, Hq, m0, sW, Hq, sA, acc);
            __syncthreads();
            if (tid == 0) {
                wait8(&f_pre0[t*4 + band]);
                if (t >= RD) wait8(&f_g1[(t-RD)*4 + band]);
            }
            __syncthreads();
            const float* pin = g_pre0r + (size_t)(t & RMASK)*BHq;
            float* dst = g_h0r + (size_t)(t & RMASK)*BHq;
            #pragma unroll
            for (int i = 0; i < 4; ++i) {
                int row = m0 + (ty << 2) + i;
                float4 p = __ldcg((const float4*)(pin + (size_t)row*Hq + col));
                float4 o;
                o.x = tanhf(acc[i][0] + p.x);
                o.y = tanhf(acc[i][1] + p.y);
                o.z = tanhf(acc[i][2] + p.z);
                o.w = tanhf(acc[i][3] + p.w);
                *(float4*)(dst + (size_t)row*Hq + col) = o;
            }
            __syncthreads();
            if (tid == 0) pub_release(&f_g0[t*4 + band]);
        }
    } else if (group == 1) {
        float4 b1 = *(const float4*)(bih1 + col);
        float4 b2 = *(const float4*)(bhh1 + col);
        for (int t = 0; t < Tq; ++t) {
            if (tid == 0) wait8(&f_g0[t*4 + band]);
            __syncthreads();
            const float* A = g_h0r + (size_t)(t & RMASK)*BHq;
            gemm64_kp(A, Hq, m0, sW, Hq, sA, acc);
            __syncthreads();
            if (tid == 0 && t >= RD) wait8(&f_g2[(t-RD)*4 + band]);
            __syncthreads();
            float* dst = g_p1r + (size_t)(t & RMASK)*BHq;
            #pragma unroll
            for (int i = 0; i < 4; ++i) {
                int row = m0 + (ty << 2) + i;
                float4 o;
                o.x = acc[i][0] + b1.x + b2.x;
                o.y = acc[i][1] + b1.y + b2.y;
                o.z = acc[i][2] + b1.z + b2.z;
                o.w = acc[i][3] + b1.w + b2.w;
                *(float4*)(dst + (size_t)row*Hq + col) = o;
            }
            __syncthreads();
            if (tid == 0) pub_release(&f_g1[t*4 + band]);
        }
    } else {
        for (int t = 0; t < Tq; ++t) {
            if (tid == 0 && t >= 1) wait8(&f_g2[(t-1)*4 + band]);    // critical wait
            __syncthreads();
            const float* A = g_h1r + (size_t)((t-1) & RMASK)*BHq;
            gemm64_kp(A, Hq, m0, sW, Hq, sA, acc);
            __syncthreads();
            if (tid == 0) wait8(&f_g1[t*4 + band]);
            __syncthreads();
            const float* pin = g_p1r + (size_t)(t & RMASK)*BHq;
            float* dst = g_h1r + (size_t)(t & RMASK)*BHq;
            #pragma unroll
            for (int i = 0; i < 4; ++i) {
                int row = m0 + (ty << 2) + i;
                float4 p = __ldcg((const float4*)(pin + (size_t)row*Hq + col));
                float4 o;
                o.x = tanhf(acc[i][0] + p.x);
                o.y = tanhf(acc[i][1] + p.y);
                o.z = tanhf(acc[i][2] + p.z);
                o.w = tanhf(acc[i][3] + p.w);
                *(float4*)(dst + (size_t)row*Hq + col) = o;
            }
            __syncthreads();
            if (tid == 0) pub_release(&f_g2[t*4 + band]);
        }
    }

    __threadfence();        // final ring stores visible to head readers
    grid_barrier(sense);    // barrier #2 (sense back to 0)

    // ---- phase 2: head (reuse low smem; 4*SCH floats << available) ----
    float* hA = smem;
    float* hW = smem + 2*SCH;

    if (blk < 8) {
        const int hm0 = (blk & 3) << 6;
        const int hn0 = (blk >> 2) << 6;
        const float* A = g_h1r + (size_t)((Tq-1) & RMASK)*BHq;
        gemm64s(A, Hq, hm0, Wf1, Hq, hn0, Hq, hA, hW, acc);
        const int hcol = hn0 + (tx << 2);
        float4 b = *(const float4*)(bf1 + hcol);
        #pragma unroll
        for (int i = 0; i < 4; ++i) {
            int row = hm0 + (ty << 2) + i;
            float4 o;
            o.x = fmaxf(acc[i][0] + b.x, 0.f);
            o.y = fmaxf(acc[i][1] + b.y, 0.f);
            o.z = fmaxf(acc[i][2] + b.z, 0.f);
            o.w = fmaxf(acc[i][3] + b.w, 0.f);
            *(float4*)(g_z1 + (size_t)row*F1q + hcol) = o;
        }
        __syncthreads();
        if (tid == 0) pub_release(&f_fc1);
    } else if (blk < 12) {
        if (tid == 0) wait8(&f_fc1);
        __syncthreads();
        const int hm0 = (blk - 8) << 6;
        gemm64s(g_z1, F1q, hm0, Wf2, F1q, 0, F1q, hA, hW, acc);
        const int hcol = tx << 2;
        float4 b = *(const float4*)(bf2 + hcol);
        #pragma unroll
        for (int i = 0; i < 4; ++i) {
            int row = hm0 + (ty << 2) + i;
            float4 o;
            o.x = acc[i][0] + b.x;
            o.y = acc[i][1] + b.y;
            o.z = acc[i][2] + b.z;
            o.w = acc[i][3] + b.w;
            *(float4*)(out + (size_t)row*Oq + hcol) = o;
        }
    }
}

// ---------------- launch ----------------
extern "C" void kernel_launch(void* const* d_in, const int* in_sizes, int n_in,
                              void* d_out, int out_size)
{
    (void)in_sizes; (void)n_in; (void)out_size;
    const float* x    = (const float*)d_in[0];
    const float* Wih0 = (const float*)d_in[1];
    const float* Whh0 = (const float*)d_in[2];
    const float* bih0 = (const float*)d_in[3];
    const float* bhh0 = (const float*)d_in[4];
    const float* Wih1 = (const float*)d_in[5];
    const float* Whh1 = (const float*)d_in[6];
    const float* bih1 = (const float*)d_in[7];
    const float* bhh1 = (const float*)d_in[8];
    const float* Wf1  = (const float*)d_in[9];
    const float* bf1  = (const float*)d_in[10];
    const float* Wf2  = (const float*)d_in[11];
    const float* bf2  = (const float*)d_in[12];
    float* out = (float*)d_out;

    cudaFuncSetAttribute(k_all, cudaFuncAttributeMaxDynamicSharedMemorySize, SMEM_ALL);

    k_all<<<NBLK, NT, SMEM_ALL>>>(x, Wih0, bih0, bhh0, Whh0,
                                  Wih1, bih1, bhh1, Whh1,
                                  Wf1, bf1, Wf2, bf2, out);
}